// round 9
// baseline (speedup 1.0000x reference)
#include <cuda_runtime.h>

#define NG 8
#define NT 2048
#define NH 2048
#define NE 8
#define CAP 320

#define NTOK (NG * NT)                 // 16384
#define OFF_PMAX   (NTOK * NE)         // 131072
#define OFF_LOGITS (OFF_PMAX + NTOK)   // 147456

#define THREADS 256                    // 8 warps, 4 tokens/warp -> 32 tok/block
#define BLOCKS (NTOK / 32)             // 512
#define BPG 64                         // blocks per group

typedef unsigned long long u64;

__device__ int g_expert_id[NTOK];
__device__ unsigned g_ctr[NG];         // monotone across graph replays

__device__ __forceinline__ void fma2(u64& d, u64 a, u64 b) {
    asm("fma.rn.f32x2 %0, %1, %2, %0;" : "+l"(d) : "l"(a), "l"(b));
}
__device__ __forceinline__ void unpack2(u64 v, float& a, float& b) {
    asm("mov.b64 {%0, %1}, %2;" : "=f"(a), "=f"(b) : "l"(v));
}

extern __shared__ u64 sW[];            // [NE][NH/2] u64 pairs = 64KB

__global__ void __launch_bounds__(THREADS, 3)
router_fused_kernel(const float* __restrict__ hs,
                    const float* __restrict__ W,
                    const float* __restrict__ bias,
                    float* __restrict__ out) {
    const int tid  = threadIdx.x;
    const int lane = tid & 31;
    const int tg   = lane >> 3;        // token group 0..3
    const int j    = lane & 7;         // H-slice lane 0..7
    const int t    = blockIdx.x * 32 + (tid >> 5) * 4 + tg;   // this lane's token

    // x pointer: 16B chunks; lane j covers bytes [j*16 + it*128] of the row
    const ulonglong2* __restrict__ xp =
        (const ulonglong2*)(hs + (size_t)t * NH) + j;

    // prefetch first two x chunks BEFORE staging barrier
    ulonglong2 xc = __ldg(xp);
    ulonglong2 xn = __ldg(xp + 8);

    // stage W into shared memory (once per block), raw 16B copies
    {
        const ulonglong2* __restrict__ wv = (const ulonglong2*)W;
        ulonglong2* __restrict__ sw2 = (ulonglong2*)sW;
#pragma unroll
        for (int k = 0; k < (NE * NH / 4) / THREADS; ++k)   // 16
            sw2[tid + k * THREADS] = __ldg(wv + tid + k * THREADS);
    }
    __syncthreads();

    u64 acc[NE];
#pragma unroll
    for (int e = 0; e < NE; ++e) acc[e] = 0ull;

    // W view: ulonglong2 index = e*512 + it*8 + j  (per expert row 1024 u64)
    const ulonglong2* __restrict__ wp = (const ulonglong2*)sW + j;

#pragma unroll 4
    for (int it = 0; it < NH / 32; ++it) {                  // 64 iterations
        ulonglong2 x2;
        if (it < NH / 32 - 2) x2 = __ldg(xp + (it + 2) * 8);

        const ulonglong2* __restrict__ w = wp + it * 8;
        // experts 0..3
        {
            ulonglong2 w0 = w[0 * 512], w1 = w[1 * 512];
            ulonglong2 w2 = w[2 * 512], w3 = w[3 * 512];
            fma2(acc[0], xc.x, w0.x); fma2(acc[1], xc.x, w1.x);
            fma2(acc[2], xc.x, w2.x); fma2(acc[3], xc.x, w3.x);
            fma2(acc[0], xc.y, w0.y); fma2(acc[1], xc.y, w1.y);
            fma2(acc[2], xc.y, w2.y); fma2(acc[3], xc.y, w3.y);
        }
        // experts 4..7
        {
            ulonglong2 w4 = w[4 * 512], w5 = w[5 * 512];
            ulonglong2 w6 = w[6 * 512], w7 = w[7 * 512];
            fma2(acc[4], xc.x, w4.x); fma2(acc[5], xc.x, w5.x);
            fma2(acc[6], xc.x, w6.x); fma2(acc[7], xc.x, w7.x);
            fma2(acc[4], xc.y, w4.y); fma2(acc[5], xc.y, w5.y);
            fma2(acc[6], xc.y, w6.y); fma2(acc[7], xc.y, w7.y);
        }
        xc = xn;
        xn = x2;
    }

    // per-lane partials: v[e] for this lane's token, H-slice j
    float v[NE];
#pragma unroll
    for (int e = 0; e < NE; ++e) {
        float a, b;
        unpack2(acc[e], a, b);
        v[e] = a + b;
    }

    // 3-step butterfly within the 8-lane j-group; distributes while reducing.
    // Final: lane j holds the full sum for expert j.
#pragma unroll
    for (int s = 0; s < 3; ++s) {
        const int off  = 4 >> s;
        const int half = 4 >> s;
        const int sel  = (j >> (2 - s)) & 1;
#pragma unroll
        for (int i = 0; i < half; ++i) {
            float a = v[i];
            float b = v[half + i];
            float mine = sel ? b : a;
            float send = sel ? a : b;
            float recv = __shfl_xor_sync(0xffffffffu, send, off);
            v[i] = mine + recv;
        }
    }

    const float l = v[0] + __ldg(bias + j);

    // coalesced logits store: warp writes 32 consecutive floats (128B)
    out[OFF_LOGITS + (size_t)t * NE + j] = l;

    // max/argmax (first-max tie-break) + softmax denom within the 8-lane group
    float mx = l;
    int am = j;
#pragma unroll
    for (int off = 1; off <= 4; off <<= 1) {
        float omx = __shfl_xor_sync(0xffffffffu, mx, off);
        int   oam = __shfl_xor_sync(0xffffffffu, am, off);
        if (omx > mx || (omx == mx && oam < am)) { mx = omx; am = oam; }
    }
    float s = __expf(l - mx);
#pragma unroll
    for (int off = 1; off <= 4; off <<= 1)
        s += __shfl_xor_sync(0xffffffffu, s, off);

    if (j == 0) {
        out[OFF_PMAX + t] = 1.0f / s;
        g_expert_id[t] = am;
    }

    // ----------------- fused capacity scan (last block of group) ------------
    __shared__ int s_g;
    __syncthreads();
    if (tid == 0) {
        __threadfence();                          // release our id writes
        const int grp = (int)(blockIdx.x / BPG);
        unsigned old = atomicAdd(&g_ctr[grp], 1u);
        s_g = (((old + 1u) & (BPG - 1u)) == 0u) ? grp : -1;
    }
    __syncthreads();
    const int g = s_g;
    if (g < 0) return;
    __threadfence();                              // acquire all id writes

    const int4* __restrict__ ids4 = (const int4*)(g_expert_id + g * NT);

    int myid[8];                                  // 2048 / 256 threads
    u64 c0 = 0ull, c1 = 0ull;
#pragma unroll
    for (int q = 0; q < 2; ++q) {
        int4 r = ids4[tid * 2 + q];
        myid[q * 4 + 0] = r.x; myid[q * 4 + 1] = r.y;
        myid[q * 4 + 2] = r.z; myid[q * 4 + 3] = r.w;
    }
#pragma unroll
    for (int i = 0; i < 8; ++i) {
        const int ee = myid[i];
        if (ee < 4) c0 += 1ull << (ee * 16);
        else        c1 += 1ull << ((ee - 4) * 16);
    }

    __shared__ u64 sA[THREADS], sB[THREADS];
    u64 i0 = c0, i1 = c1;
    sA[tid] = i0; sB[tid] = i1;
    __syncthreads();
#pragma unroll
    for (int off = 1; off < THREADS; off <<= 1) {
        u64 a = 0ull, b = 0ull;
        if (tid >= off) { a = sA[tid - off]; b = sB[tid - off]; }
        __syncthreads();
        i0 += a; i1 += b;
        sA[tid] = i0; sB[tid] = i1;
        __syncthreads();
    }
    u64 r0 = i0 - c0, r1 = i1 - c1;               // exclusive prefix

    __shared__ unsigned char sflag[NT];           // eid (3b) | keep (bit 3)
#pragma unroll
    for (int i = 0; i < 8; ++i) {
        const int ee = myid[i];
        int prio;
        if (ee < 4) { r0 += 1ull << (ee * 16);       prio = (int)((r0 >> (ee * 16)) & 0xFFFF); }
        else        { r1 += 1ull << ((ee - 4) * 16); prio = (int)((r1 >> ((ee - 4) * 16)) & 0xFFFF); }
        sflag[tid * 8 + i] = (unsigned char)(ee | ((prio <= CAP) ? 8 : 0));
    }
    __syncthreads();

    // coalesced one-hot write: 256 threads write consecutive float4
    float4* __restrict__ dst = (float4*)out + (size_t)g * NT * 2;
    for (int k = tid; k < NT * 2; k += THREADS) {
        const int fl   = sflag[k >> 1];
        const int ee   = fl & 7;
        const float kp = (fl & 8) ? 1.0f : 0.0f;
        const int rel  = ee - (k & 1) * 4;
        float4 v4 = make_float4(0.f, 0.f, 0.f, 0.f);
        if (rel >= 0 && rel < 4) (&v4.x)[rel] = kp;
        dst[k] = v4;
    }
}

extern "C" void kernel_launch(void* const* d_in, const int* in_sizes, int n_in,
                              void* d_out, int out_size) {
    const float* hs   = (const float*)d_in[0];
    const float* W    = (const float*)d_in[1];
    const float* bias = (const float*)d_in[2];
    float* out = (float*)d_out;

    static const int SMEM = NE * NH * (int)sizeof(float);   // 64KB dynamic
    cudaFuncSetAttribute(router_fused_kernel,
                         cudaFuncAttributeMaxDynamicSharedMemorySize, SMEM);
    router_fused_kernel<<<BLOCKS, THREADS, SMEM>>>(hs, W, bias, out);
}

// round 10
// speedup vs baseline: 1.0792x; 1.0792x over previous
#include <cuda_runtime.h>

#define NG 8
#define NT 2048
#define NH 2048
#define NE 8
#define CAP 320

#define NTOK (NG * NT)                 // 16384
#define OFF_PMAX   (NTOK * NE)         // 131072
#define OFF_LOGITS (OFF_PMAX + NTOK)   // 147456

#define TPW 8                          // tokens per warp
#define THREADS 256                    // 8 warps -> 64 tokens per block
#define BLOCKS (NTOK / (TPW * 8))      // 256
#define BPG (BLOCKS / NG)              // 32 blocks per group

typedef unsigned long long u64;

__device__ int g_expert_id[NTOK];
__device__ unsigned g_ctr[NG];         // monotone across graph replays

__device__ __forceinline__ u64 pack2(float a, float b) {
    u64 r;
    asm("mov.b64 %0, {%1, %2};" : "=l"(r) : "f"(a), "f"(b));
    return r;
}
__device__ __forceinline__ u64 dup2(float a) {
    u64 r;
    asm("mov.b64 %0, {%1, %1};" : "=l"(r) : "f"(a));
    return r;
}
__device__ __forceinline__ void unpack2(u64 v, float& a, float& b) {
    asm("mov.b64 {%0, %1}, %2;" : "=f"(a), "=f"(b) : "l"(v));
}
__device__ __forceinline__ void fma2(u64& d, u64 a, u64 b) {
    asm("fma.rn.f32x2 %0, %1, %2, %0;" : "+l"(d) : "l"(a), "l"(b));
}
__device__ __forceinline__ u64 add2(u64 a, u64 b) {
    u64 r;
    asm("add.rn.f32x2 %0, %1, %2;" : "=l"(r) : "l"(a), "l"(b));
    return r;
}

// W transposed, expert-paired: sWp[ep*2048 + h] = (W[2ep][h], W[2ep+1][h])
extern __shared__ u64 sWp[];           // 4 * 2048 u64 = 64KB

__global__ void __launch_bounds__(THREADS, 2)
router_fused_kernel(const float* __restrict__ hs,
                    const float* __restrict__ W,
                    const float* __restrict__ bias,
                    float* __restrict__ out) {
    const int tid  = threadIdx.x;
    const int lane = tid & 31;
    const int t0   = ((blockIdx.x * THREADS + tid) >> 5) * TPW;  // warp's 8 tokens

    // x base: lane j reads h = it*32 + j for each of its 8 tokens
    const float* __restrict__ xb = hs + (size_t)t0 * NH + lane;

    // prefetch iterations 0 and 1 BEFORE the staging barrier
    float xc[TPW], xn[TPW];
#pragma unroll
    for (int k = 0; k < TPW; ++k) xc[k] = __ldg(xb + k * NH);
#pragma unroll
    for (int k = 0; k < TPW; ++k) xn[k] = __ldg(xb + k * NH + 32);

    // stage W^T expert-paired into shared memory
    for (int k = tid; k < 4 * NH; k += THREADS) {       // 32 iterations
        const int ep = k >> 11, h = k & (NH - 1);
        const float a = __ldg(W + (2 * ep) * NH + h);
        const float b = __ldg(W + (2 * ep + 1) * NH + h);
        sWp[k] = pack2(a, b);
    }
    __syncthreads();

    // acc[tok][ep] = f32x2 (expert 2ep, expert 2ep+1). 64 registers.
    u64 acc[TPW][4];
#pragma unroll
    for (int k = 0; k < TPW; ++k)
#pragma unroll
        for (int ep = 0; ep < 4; ++ep) acc[k][ep] = 0ull;

    const u64* __restrict__ wp = sWp + lane;

#pragma unroll 2
    for (int it = 0; it < NH / 32; ++it) {              // 64 iterations
        // prefetch it+2 (depth-2 pipeline)
        float xf[TPW];
        if (it < NH / 32 - 2) {
            const int o = (it + 2) * 32;
#pragma unroll
            for (int k = 0; k < TPW; ++k) xf[k] = __ldg(xb + k * NH + o);
        }
        // W for this lane's h: 4 conflict-free LDS.64
        const u64 w0 = wp[it * 32 + 0 * NH];
        const u64 w1 = wp[it * 32 + 1 * NH];
        const u64 w2 = wp[it * 32 + 2 * NH];
        const u64 w3 = wp[it * 32 + 3 * NH];
#pragma unroll
        for (int k = 0; k < TPW; ++k) {
            const u64 xd = dup2(xc[k]);
            fma2(acc[k][0], xd, w0);
            fma2(acc[k][1], xd, w1);
            fma2(acc[k][2], xd, w2);
            fma2(acc[k][3], xd, w3);
        }
#pragma unroll
        for (int k = 0; k < TPW; ++k) { xc[k] = xn[k]; xn[k] = xf[k]; }
    }

    // packed butterfly reduction over 32 lanes, 32 u64 values per lane.
    // value index v = tok*4 + ep; after 5 steps lane L holds total for v = L.
    u64 r[32];
#pragma unroll
    for (int k = 0; k < TPW; ++k)
#pragma unroll
        for (int ep = 0; ep < 4; ++ep) r[k * 4 + ep] = acc[k][ep];

#pragma unroll
    for (int s = 0; s < 5; ++s) {
        const int off  = 16 >> s;
        const int half = 16 >> s;
        const int sel  = (lane >> (4 - s)) & 1;
#pragma unroll
        for (int i = 0; i < half; ++i) {
            const u64 a = r[i];
            const u64 b = r[half + i];
            const u64 mine = sel ? b : a;
            const u64 send = sel ? a : b;
            const u64 recv = __shfl_xor_sync(0xffffffffu, send, off);
            r[i] = add2(mine, recv);
        }
    }

    const int kk = lane >> 2;          // token offset 0..7
    const int ep = lane & 3;           // expert pair 0..3
    const int t  = t0 + kk;

    const float2 bb = __ldg((const float2*)bias + ep);
    const u64 l64 = add2(r[0], pack2(bb.x, bb.y));
    float lo, hi;
    unpack2(l64, lo, hi);

    // coalesced logits store: warp writes 64 consecutive floats (256B)
    *(float2*)(out + OFF_LOGITS + (size_t)t0 * NE + 2 * lane) = make_float2(lo, hi);

    // max/argmax (first-max tie-break) + softmax denom within 4-lane groups
    const int e0 = 2 * ep;
    float mx;
    int am;
    if (hi > lo) { mx = hi; am = e0 + 1; } else { mx = lo; am = e0; }
#pragma unroll
    for (int off = 1; off <= 2; off <<= 1) {
        const float omx = __shfl_xor_sync(0xffffffffu, mx, off);
        const int   oam = __shfl_xor_sync(0xffffffffu, am, off);
        if (omx > mx || (omx == mx && oam < am)) { mx = omx; am = oam; }
    }
    float s = __expf(lo - mx) + __expf(hi - mx);
    s += __shfl_xor_sync(0xffffffffu, s, 1);
    s += __shfl_xor_sync(0xffffffffu, s, 2);

    if (ep == 0) {
        out[OFF_PMAX + t] = 1.0f / s;
        g_expert_id[t] = am;
    }

    // ----------------- fused capacity scan (last block of group) ------------
    __shared__ int s_g;
    __syncthreads();
    if (tid == 0) {
        __threadfence();                          // release our id writes
        const int grp = (int)(blockIdx.x / BPG);
        const unsigned old = atomicAdd(&g_ctr[grp], 1u);
        s_g = (((old + 1u) & (BPG - 1u)) == 0u) ? grp : -1;
    }
    __syncthreads();
    const int g = s_g;
    if (g < 0) return;
    __threadfence();                              // acquire all id writes

    const int4* __restrict__ ids4 = (const int4*)(g_expert_id + g * NT);

    int myid[8];                                  // 2048 / 256 threads
    u64 c0 = 0ull, c1 = 0ull;
#pragma unroll
    for (int q = 0; q < 2; ++q) {
        const int4 rr = ids4[tid * 2 + q];
        myid[q * 4 + 0] = rr.x; myid[q * 4 + 1] = rr.y;
        myid[q * 4 + 2] = rr.z; myid[q * 4 + 3] = rr.w;
    }
#pragma unroll
    for (int i = 0; i < 8; ++i) {
        const int ee = myid[i];
        if (ee < 4) c0 += 1ull << (ee * 16);
        else        c1 += 1ull << ((ee - 4) * 16);
    }

    __shared__ u64 sA[THREADS], sB[THREADS];
    u64 i0 = c0, i1 = c1;
    sA[tid] = i0; sB[tid] = i1;
    __syncthreads();
#pragma unroll
    for (int off = 1; off < THREADS; off <<= 1) {
        u64 a = 0ull, b = 0ull;
        if (tid >= off) { a = sA[tid - off]; b = sB[tid - off]; }
        __syncthreads();
        i0 += a; i1 += b;
        sA[tid] = i0; sB[tid] = i1;
        __syncthreads();
    }
    u64 r0 = i0 - c0, r1 = i1 - c1;               // exclusive prefix

    __shared__ unsigned char sflag[NT];           // eid (3b) | keep (bit 3)
#pragma unroll
    for (int i = 0; i < 8; ++i) {
        const int ee = myid[i];
        int prio;
        if (ee < 4) { r0 += 1ull << (ee * 16);       prio = (int)((r0 >> (ee * 16)) & 0xFFFF); }
        else        { r1 += 1ull << ((ee - 4) * 16); prio = (int)((r1 >> ((ee - 4) * 16)) & 0xFFFF); }
        sflag[tid * 8 + i] = (unsigned char)(ee | ((prio <= CAP) ? 8 : 0));
    }
    __syncthreads();

    // coalesced one-hot write: 256 threads write consecutive float4
    float4* __restrict__ dst = (float4*)out + (size_t)g * NT * 2;
    for (int k = tid; k < NT * 2; k += THREADS) {
        const int fl   = sflag[k >> 1];
        const int ee   = fl & 7;
        const float kp = (fl & 8) ? 1.0f : 0.0f;
        const int rel  = ee - (k & 1) * 4;
        float4 v4 = make_float4(0.f, 0.f, 0.f, 0.f);
        if (rel >= 0 && rel < 4) (&v4.x)[rel] = kp;
        dst[k] = v4;
    }
}

extern "C" void kernel_launch(void* const* d_in, const int* in_sizes, int n_in,
                              void* d_out, int out_size) {
    const float* hs   = (const float*)d_in[0];
    const float* W    = (const float*)d_in[1];
    const float* bias = (const float*)d_in[2];
    float* out = (float*)d_out;

    static const int SMEM = 4 * NH * (int)sizeof(u64);   // 64KB dynamic
    cudaFuncSetAttribute(router_fused_kernel,
                         cudaFuncAttributeMaxDynamicSharedMemorySize, SMEM);
    router_fused_kernel<<<BLOCKS, THREADS, SMEM>>>(hs, W, bias, out);
}

// round 11
// speedup vs baseline: 1.1291x; 1.0462x over previous
#include <cuda_runtime.h>

#define NG 8
#define NT 2048
#define NH 2048
#define NE 8
#define CAP 320

#define NTOK (NG * NT)                 // 16384
#define OFF_PMAX   (NTOK * NE)         // 131072
#define OFF_LOGITS (OFF_PMAX + NTOK)   // 147456

#define TPW 4                          // tokens per warp
#define THREADS 256                    // 8 warps -> 32 tokens per block
#define BLOCKS (NTOK / (TPW * 8))      // 512
#define BPG (BLOCKS / NG)              // 64 blocks per group

typedef unsigned long long u64;

__device__ int g_expert_id[NTOK];
__device__ unsigned g_ctr[NG];         // monotone across graph replays

__device__ __forceinline__ u64 pack2(float a, float b) {
    u64 r;
    asm("mov.b64 %0, {%1, %2};" : "=l"(r) : "f"(a), "f"(b));
    return r;
}
__device__ __forceinline__ u64 dup2(float a) {
    u64 r;
    asm("mov.b64 %0, {%1, %1};" : "=l"(r) : "f"(a));
    return r;
}
__device__ __forceinline__ void unpack2(u64 v, float& a, float& b) {
    asm("mov.b64 {%0, %1}, %2;" : "=f"(a), "=f"(b) : "l"(v));
}
__device__ __forceinline__ void fma2(u64& d, u64 a, u64 b) {
    asm("fma.rn.f32x2 %0, %1, %2, %0;" : "+l"(d) : "l"(a), "l"(b));
}
__device__ __forceinline__ u64 add2(u64 a, u64 b) {
    u64 r;
    asm("add.rn.f32x2 %0, %1, %2;" : "=l"(r) : "l"(a), "l"(b));
    return r;
}

// W transposed, expert-paired: sWp[ep*NH + h] = (W[2ep][h], W[2ep+1][h])
extern __shared__ u64 sWp[];           // 4 * 2048 u64 = 64KB

__global__ void __launch_bounds__(THREADS, 3)
router_fused_kernel(const float* __restrict__ hs,
                    const float* __restrict__ W,
                    const float* __restrict__ bias,
                    float* __restrict__ out) {
    const int tid  = threadIdx.x;
    const int lane = tid & 31;
    const int t0   = ((blockIdx.x * THREADS + tid) >> 5) * TPW;

    // x: lane owns h = it*64 + 2*lane (+1); float2 per token per iter
    const float2* __restrict__ xp =
        (const float2*)(hs + (size_t)t0 * NH) + lane;   // token k at +k*1024

    // prefetch iterations 0 and 1 BEFORE the staging barrier
    float2 xc[TPW], xn[TPW];
#pragma unroll
    for (int k = 0; k < TPW; ++k) xc[k] = __ldg(xp + k * (NH / 2));
#pragma unroll
    for (int k = 0; k < TPW; ++k) xn[k] = __ldg(xp + k * (NH / 2) + 32);

    // stage W^T expert-paired into shared memory
    for (int k = tid; k < 4 * NH; k += THREADS) {        // 32 iterations
        const int ep = k >> 11, h = k & (NH - 1);
        const float a = __ldg(W + (2 * ep) * NH + h);
        const float b = __ldg(W + (2 * ep + 1) * NH + h);
        sWp[k] = pack2(a, b);
    }
    __syncthreads();

    // acc[tok][ep] = f32x2 (expert 2ep, expert 2ep+1). 32 registers.
    u64 acc[TPW][4];
#pragma unroll
    for (int k = 0; k < TPW; ++k)
#pragma unroll
        for (int ep = 0; ep < 4; ++ep) acc[k][ep] = 0ull;

    const u64* __restrict__ wp = sWp + 2 * lane;         // lane's h pair

#pragma unroll 4
    for (int it = 0; it < NH / 64; ++it) {               // 32 iterations
        // rotate pipeline: compute with xc, xn in flight, prefetch it+2
        float2 xf[TPW];
        if (it < NH / 64 - 2) {
#pragma unroll
            for (int k = 0; k < TPW; ++k)
                xf[k] = __ldg(xp + k * (NH / 2) + (it + 2) * 32);
        }
        // broadcast-dup x for both h's of this lane
        u64 xd0[TPW], xd1[TPW];
#pragma unroll
        for (int k = 0; k < TPW; ++k) {
            xd0[k] = dup2(xc[k].x);
            xd1[k] = dup2(xc[k].y);
        }
#pragma unroll
        for (int ep = 0; ep < 4; ++ep) {
            // LDS.128: W pairs for h = it*64 + 2*lane, +1 (conflict-free)
            const ulonglong2 w2 =
                *(const ulonglong2*)(wp + ep * NH + it * 64);
#pragma unroll
            for (int k = 0; k < TPW; ++k) {
                fma2(acc[k][ep], xd0[k], w2.x);
                fma2(acc[k][ep], xd1[k], w2.y);
            }
        }
#pragma unroll
        for (int k = 0; k < TPW; ++k) { xc[k] = xn[k]; xn[k] = xf[k]; }
    }

    // packed butterfly reduction: 16 u64 values over 32 lanes.
    // After 4 steps + xor-1 combine, lane L holds value idx16=(L>>1)&15
    // (duplicated across bit0), idx16 = tok*4 + ep.
    u64 r[16];
#pragma unroll
    for (int k = 0; k < TPW; ++k)
#pragma unroll
        for (int ep = 0; ep < 4; ++ep) r[k * 4 + ep] = acc[k][ep];

#pragma unroll
    for (int s = 0; s < 4; ++s) {
        const int off  = 16 >> s;
        const int half = 8 >> s;
        const int sel  = (lane >> (4 - s)) & 1;
#pragma unroll
        for (int i = 0; i < half; ++i) {
            const u64 a = r[i];
            const u64 b = r[half + i];
            const u64 mine = sel ? b : a;
            const u64 send = sel ? a : b;
            const u64 recv = __shfl_xor_sync(0xffffffffu, send, off);
            r[i] = add2(mine, recv);
        }
    }
    r[0] = add2(r[0], __shfl_xor_sync(0xffffffffu, r[0], 1));

    const int idx16 = (lane >> 1) & 15;
    const int tok = idx16 >> 2;        // lane bits 3,4
    const int ep  = idx16 & 3;         // lane bits 1,2
    const int t   = t0 + tok;

    const float2 bb = __ldg((const float2*)bias + ep);
    const u64 l64 = add2(r[0], pack2(bb.x, bb.y));
    float lo, hi;
    unpack2(l64, lo, hi);

    // fully coalesced logits store: float index t0*8 + lane (128B per warp)
    out[OFF_LOGITS + (size_t)t0 * NE + lane] = (lane & 1) ? hi : lo;

    // max/argmax (first-max tie-break) + softmax denom across ep lanes
    const int e0 = 2 * ep;
    float mx;
    int am;
    if (hi > lo) { mx = hi; am = e0 + 1; } else { mx = lo; am = e0; }
#pragma unroll
    for (int off = 2; off <= 4; off <<= 1) {
        const float omx = __shfl_xor_sync(0xffffffffu, mx, off);
        const int   oam = __shfl_xor_sync(0xffffffffu, am, off);
        if (omx > mx || (omx == mx && oam < am)) { mx = omx; am = oam; }
    }
    float s = __expf(lo - mx) + __expf(hi - mx);
    s += __shfl_xor_sync(0xffffffffu, s, 2);
    s += __shfl_xor_sync(0xffffffffu, s, 4);

    if ((lane & 7) == 0) {             // ep==0 && bit0==0; tok = lane>>3
        out[OFF_PMAX + t] = 1.0f / s;
        g_expert_id[t] = am;
    }

    // ----------------- fused capacity scan (last block of group) ------------
    __shared__ int s_g;
    __syncthreads();
    if (tid == 0) {
        __threadfence();                          // release our id writes
        const int grp = (int)(blockIdx.x / BPG);
        const unsigned old = atomicAdd(&g_ctr[grp], 1u);
        s_g = (((old + 1u) & (BPG - 1u)) == 0u) ? grp : -1;
    }
    __syncthreads();
    const int g = s_g;
    if (g < 0) return;
    __threadfence();                              // acquire all id writes

    const int4* __restrict__ ids4 = (const int4*)(g_expert_id + g * NT);

    int myid[8];                                  // 2048 / 256 threads
    u64 c0 = 0ull, c1 = 0ull;
#pragma unroll
    for (int q = 0; q < 2; ++q) {
        const int4 rr = ids4[tid * 2 + q];
        myid[q * 4 + 0] = rr.x; myid[q * 4 + 1] = rr.y;
        myid[q * 4 + 2] = rr.z; myid[q * 4 + 3] = rr.w;
    }
#pragma unroll
    for (int i = 0; i < 8; ++i) {
        const int ee = myid[i];
        if (ee < 4) c0 += 1ull << (ee * 16);
        else        c1 += 1ull << ((ee - 4) * 16);
    }

    __shared__ u64 sA[THREADS], sB[THREADS];
    u64 i0 = c0, i1 = c1;
    sA[tid] = i0; sB[tid] = i1;
    __syncthreads();
#pragma unroll
    for (int off = 1; off < THREADS; off <<= 1) {
        u64 a = 0ull, b = 0ull;
        if (tid >= off) { a = sA[tid - off]; b = sB[tid - off]; }
        __syncthreads();
        i0 += a; i1 += b;
        sA[tid] = i0; sB[tid] = i1;
        __syncthreads();
    }
    u64 r0 = i0 - c0, r1 = i1 - c1;               // exclusive prefix

    __shared__ unsigned char sflag[NT];           // eid (3b) | keep (bit 3)
#pragma unroll
    for (int i = 0; i < 8; ++i) {
        const int ee = myid[i];
        int prio;
        if (ee < 4) { r0 += 1ull << (ee * 16);       prio = (int)((r0 >> (ee * 16)) & 0xFFFF); }
        else        { r1 += 1ull << ((ee - 4) * 16); prio = (int)((r1 >> ((ee - 4) * 16)) & 0xFFFF); }
        sflag[tid * 8 + i] = (unsigned char)(ee | ((prio <= CAP) ? 8 : 0));
    }
    __syncthreads();

    // coalesced one-hot write: 256 threads write consecutive float4
    float4* __restrict__ dst = (float4*)out + (size_t)g * NT * 2;
    for (int k = tid; k < NT * 2; k += THREADS) {
        const int fl   = sflag[k >> 1];
        const int ee   = fl & 7;
        const float kp = (fl & 8) ? 1.0f : 0.0f;
        const int rel  = ee - (k & 1) * 4;
        float4 v4 = make_float4(0.f, 0.f, 0.f, 0.f);
        if (rel >= 0 && rel < 4) (&v4.x)[rel] = kp;
        dst[k] = v4;
    }
}

extern "C" void kernel_launch(void* const* d_in, const int* in_sizes, int n_in,
                              void* d_out, int out_size) {
    const float* hs   = (const float*)d_in[0];
    const float* W    = (const float*)d_in[1];
    const float* bias = (const float*)d_in[2];
    float* out = (float*)d_out;

    static const int SMEM = 4 * NH * (int)sizeof(u64);   // 64KB dynamic
    cudaFuncSetAttribute(router_fused_kernel,
                         cudaFuncAttributeMaxDynamicSharedMemorySize, SMEM);
    router_fused_kernel<<<BLOCKS, THREADS, SMEM>>>(hs, W, bias, out);
}

// round 12
// speedup vs baseline: 1.3834x; 1.2252x over previous
#include <cuda_runtime.h>

#define NG 8
#define NT 2048
#define NH 2048
#define NE 8
#define CAP 320

#define NTOK (NG * NT)                 // 16384
#define OFF_PMAX   (NTOK * NE)         // 131072
#define OFF_LOGITS (OFF_PMAX + NTOK)   // 147456

#define TPW 4                          // tokens per warp
#define THREADS 256                    // 8 warps -> 32 tokens per block
#define BLOCKS (NTOK / (TPW * 8))      // 512
#define BPG (BLOCKS / NG)              // 64 blocks per group

typedef unsigned long long u64;

__device__ int g_expert_id[NTOK];
__device__ unsigned g_ctr[NG];         // monotone across graph replays

__device__ __forceinline__ u64 pack2(float a, float b) {
    u64 r;
    asm("mov.b64 %0, {%1, %2};" : "=l"(r) : "f"(a), "f"(b));
    return r;
}
__device__ __forceinline__ void unpack2(u64 v, float& a, float& b) {
    asm("mov.b64 {%0, %1}, %2;" : "=f"(a), "=f"(b) : "l"(v));
}
__device__ __forceinline__ void fma2(u64& d, u64 a, u64 b) {
    asm("fma.rn.f32x2 %0, %1, %2, %0;" : "+l"(d) : "l"(a), "l"(b));
}

extern __shared__ float4 sW[];         // [NE][NH/4] = 4096 float4 = 64KB

__global__ void __launch_bounds__(THREADS, 2)
router_fused_kernel(const float* __restrict__ hs,
                    const float* __restrict__ W,
                    const float* __restrict__ bias,
                    float* __restrict__ out) {
    const int tid  = threadIdx.x;
    const int lane = tid & 31;
    const int t0   = ((blockIdx.x * THREADS + tid) >> 5) * TPW;

    const float4* __restrict__ xb = (const float4*)hs + (size_t)t0 * (NH / 4);

    // explicit depth-2 ping-pong prefetch; iters 0 and 1 issued BEFORE the
    // W-staging barrier so DRAM latency overlaps the staging phase.
    float4 xc[TPW], xn[TPW];
#pragma unroll
    for (int k = 0; k < TPW; ++k) xc[k] = __ldg(xb + k * (NH / 4) + lane);
#pragma unroll
    for (int k = 0; k < TPW; ++k) xn[k] = __ldg(xb + k * (NH / 4) + 32 + lane);

    // stage W into shared memory (once per block)
    {
        const float4* __restrict__ wv = (const float4*)W;
#pragma unroll
        for (int k = 0; k < (NE * NH / 4) / THREADS; ++k)   // 16
            sW[tid + k * THREADS] = __ldg(wv + tid + k * THREADS);
    }
    __syncthreads();

    // acc[tok][e], f32x2 packed along H. 64 registers.
    u64 acc[TPW][NE];
#pragma unroll
    for (int tk = 0; tk < TPW; ++tk)
#pragma unroll
        for (int e = 0; e < NE; ++e) acc[tk][e] = 0ull;

#pragma unroll 2
    for (int it = 0; it < NH / (32 * 4); ++it) {            // 16 iterations
        // prefetch it+2 (keeps 8 LDG.128 in flight per warp)
        float4 xf[TPW];
        if (it < NH / (32 * 4) - 2) {
            const int nidx = (it + 2) * 32 + lane;
#pragma unroll
            for (int k = 0; k < TPW; ++k)
                xf[k] = __ldg(xb + k * (NH / 4) + nidx);
        }
        // x pairs: float4 register quads are already aligned pairs
        u64 xlo[TPW], xhi[TPW];
#pragma unroll
        for (int k = 0; k < TPW; ++k) {
            xlo[k] = pack2(xc[k].x, xc[k].y);
            xhi[k] = pack2(xc[k].z, xc[k].w);
        }
        const int idx = it * 32 + lane;
#pragma unroll
        for (int e = 0; e < NE; ++e) {
            const float4 w = sW[e * (NH / 4) + idx];
            const u64 wlo = pack2(w.x, w.y);
            const u64 whi = pack2(w.z, w.w);
#pragma unroll
            for (int k = 0; k < TPW; ++k) {
                fma2(acc[k][e], xlo[k], wlo);
                fma2(acc[k][e], xhi[k], whi);
            }
        }
#pragma unroll
        for (int k = 0; k < TPW; ++k) { xc[k] = xn[k]; xn[k] = xf[k]; }
    }

    // v[t*8+e]: 32 partial sums per lane
    float v[32];
#pragma unroll
    for (int tk = 0; tk < TPW; ++tk)
#pragma unroll
        for (int e = 0; e < NE; ++e) {
            float a, b;
            unpack2(acc[tk][e], a, b);
            v[tk * 8 + e] = a + b;
        }

    // 5-step butterfly: reduces across 32 lanes while distributing results.
    // Final: lane L holds the total for value index L (token L>>3, expert L&7).
#pragma unroll
    for (int s = 0; s < 5; ++s) {
        const int off  = 16 >> s;
        const int half = 16 >> s;
        const int sel  = (lane >> (4 - s)) & 1;
#pragma unroll
        for (int i = 0; i < half; ++i) {
            const float a = v[i];
            const float b = v[half + i];
            const float mine = sel ? b : a;
            const float send = sel ? a : b;
            const float recv = __shfl_xor_sync(0xffffffffu, send, off);
            v[i] = mine + recv;
        }
    }

    const int e = lane & 7;
    const int t = t0 + (lane >> 3);
    const float l = v[0] + __ldg(bias + e);

    // fully coalesced logits store: 32 consecutive floats per warp (128B)
    out[OFF_LOGITS + (size_t)t0 * NE + lane] = l;

    // max/argmax (first-max tie-break) + softmax denom within 8-lane groups
    float mx = l;
    int am = e;
#pragma unroll
    for (int off = 1; off <= 4; off <<= 1) {
        const float omx = __shfl_xor_sync(0xffffffffu, mx, off);
        const int   oam = __shfl_xor_sync(0xffffffffu, am, off);
        if (omx > mx || (omx == mx && oam < am)) { mx = omx; am = oam; }
    }
    float s = __expf(l - mx);
#pragma unroll
    for (int off = 1; off <= 4; off <<= 1)
        s += __shfl_xor_sync(0xffffffffu, s, off);

    if (e == 0) {
        out[OFF_PMAX + t] = 1.0f / s;
        g_expert_id[t] = am;
    }

    // ----------------- fused capacity scan (last block of group) ------------
    __shared__ int s_g;
    __syncthreads();
    if (tid == 0) {
        __threadfence();                          // release our id writes
        const int grp = (int)(blockIdx.x / BPG);
        const unsigned old = atomicAdd(&g_ctr[grp], 1u);
        s_g = (((old + 1u) & (BPG - 1u)) == 0u) ? grp : -1;
    }
    __syncthreads();
    const int g = s_g;
    if (g < 0) return;
    __threadfence();                              // acquire all id writes

    const int4* __restrict__ ids4 = (const int4*)(g_expert_id + g * NT);

    int myid[8];                                  // 2048 / 256 threads
    u64 c0 = 0ull, c1 = 0ull;
#pragma unroll
    for (int q = 0; q < 2; ++q) {
        const int4 rr = ids4[tid * 2 + q];
        myid[q * 4 + 0] = rr.x; myid[q * 4 + 1] = rr.y;
        myid[q * 4 + 2] = rr.z; myid[q * 4 + 3] = rr.w;
    }
#pragma unroll
    for (int i = 0; i < 8; ++i) {
        const int ee = myid[i];
        if (ee < 4) c0 += 1ull << (ee * 16);
        else        c1 += 1ull << ((ee - 4) * 16);
    }

    __shared__ u64 sA[THREADS], sB[THREADS];
    u64 i0 = c0, i1 = c1;
    sA[tid] = i0; sB[tid] = i1;
    __syncthreads();
#pragma unroll
    for (int off = 1; off < THREADS; off <<= 1) {
        u64 a = 0ull, b = 0ull;
        if (tid >= off) { a = sA[tid - off]; b = sB[tid - off]; }
        __syncthreads();
        i0 += a; i1 += b;
        sA[tid] = i0; sB[tid] = i1;
        __syncthreads();
    }
    u64 r0 = i0 - c0, r1 = i1 - c1;               // exclusive prefix

    __shared__ unsigned char sflag[NT];           // eid (3b) | keep (bit 3)
#pragma unroll
    for (int i = 0; i < 8; ++i) {
        const int ee = myid[i];
        int prio;
        if (ee < 4) { r0 += 1ull << (ee * 16);       prio = (int)((r0 >> (ee * 16)) & 0xFFFF); }
        else        { r1 += 1ull << ((ee - 4) * 16); prio = (int)((r1 >> ((ee - 4) * 16)) & 0xFFFF); }
        sflag[tid * 8 + i] = (unsigned char)(ee | ((prio <= CAP) ? 8 : 0));
    }
    __syncthreads();

    // coalesced one-hot write: 256 threads write consecutive float4
    float4* __restrict__ dst = (float4*)out + (size_t)g * NT * 2;
    for (int k = tid; k < NT * 2; k += THREADS) {
        const int fl   = sflag[k >> 1];
        const int ee   = fl & 7;
        const float kp = (fl & 8) ? 1.0f : 0.0f;
        const int rel  = ee - (k & 1) * 4;
        float4 v4 = make_float4(0.f, 0.f, 0.f, 0.f);
        if (rel >= 0 && rel < 4) (&v4.x)[rel] = kp;
        dst[k] = v4;
    }
}

extern "C" void kernel_launch(void* const* d_in, const int* in_sizes, int n_in,
                              void* d_out, int out_size) {
    const float* hs   = (const float*)d_in[0];
    const float* W    = (const float*)d_in[1];
    const float* bias = (const float*)d_in[2];
    float* out = (float*)d_out;

    static const int SMEM = NE * NH * (int)sizeof(float);   // 64KB dynamic
    cudaFuncSetAttribute(router_fused_kernel,
                         cudaFuncAttributeMaxDynamicSharedMemorySize, SMEM);
    router_fused_kernel<<<BLOCKS, THREADS, SMEM>>>(hs, W, bias, out);
}